// round 10
// baseline (speedup 1.0000x reference)
#include <cuda_runtime.h>
#include <cuda_bf16.h>
#include <math.h>

#define EPSV 1e-5f
constexpr int B_ = 4, C_ = 64, N_ = 4096, OUT_ = 128, K_ = 20;
constexpr int HB_ = 16;   // C/4

typedef unsigned long long ull;

// ---------------- scratch (device globals; no allocation allowed) ----------
__device__ __align__(16) __nv_bfloat16 g_pbf[B_ * N_ * 128];  // [B][N][hi64|lo64]
__device__ float g_sq [B_ * N_];                  // squared norms (exact fp32)
__device__ float g_hb [B_ * N_ * HB_];            // bottleneck features [B][N][16]
__device__ int   g_idx[B_ * N_ * K_];             // knn indices
__device__ float g_d2 [(size_t)B_ * N_ * N_];     // 268MB distance matrix
__device__ float g_Wres[OUT_ * C_], g_bres[OUT_];
__device__ float g_Wbot[HB_ * C_],  g_bbot[HB_];
__device__ float g_Wg1[32 * 32],    g_bg1[32];
__device__ float g_Wg2[32 * 32],    g_bg2[32];
__device__ float g_Wdec[OUT_ * 96], g_bdec[OUT_];

struct Params { const float* p[26]; };

// ---------------- mma helpers ----------------------------------------------
__device__ __forceinline__ void ldsm4(unsigned& r0, unsigned& r1, unsigned& r2, unsigned& r3,
                                      unsigned addr) {
    asm volatile("ldmatrix.sync.aligned.m8n8.x4.shared.b16 {%0,%1,%2,%3}, [%4];"
                 : "=r"(r0), "=r"(r1), "=r"(r2), "=r"(r3) : "r"(addr));
}
__device__ __forceinline__ void mma16816(float* c, const unsigned* a, unsigned b0, unsigned b1) {
    asm volatile("mma.sync.aligned.m16n8k16.row.col.f32.bf16.bf16.f32 "
                 "{%0,%1,%2,%3}, {%4,%5,%6,%7}, {%8,%9}, {%0,%1,%2,%3};"
                 : "+f"(c[0]), "+f"(c[1]), "+f"(c[2]), "+f"(c[3])
                 : "r"(a[0]), "r"(a[1]), "r"(a[2]), "r"(a[3]), "r"(b0), "r"(b1));
}

// ---------------- kernel 0: fold BN into conv weights ----------------------
__global__ void fold_kernel(Params P) {
    const int tid = threadIdx.x;
    {   const float *W = P.p[1], *g = P.p[2], *b = P.p[3], *m = P.p[4], *v = P.p[5];
        for (int i = tid; i < OUT_ * C_; i += 256) {
            int o = i >> 6;
            g_Wres[i] = W[i] * (g[o] / sqrtf(v[o] + EPSV));
        }
        for (int o = tid; o < OUT_; o += 256) {
            float s = g[o] / sqrtf(v[o] + EPSV);
            g_bres[o] = b[o] - m[o] * s;
        }
    }
    {   const float *W = P.p[6], *g = P.p[7], *b = P.p[8], *m = P.p[9], *v = P.p[10];
        for (int i = tid; i < HB_ * C_; i += 256) {
            int o = i >> 6;
            g_Wbot[i] = W[i] * (g[o] / sqrtf(v[o] + EPSV));
        }
        for (int o = tid; o < HB_; o += 256) {
            float s = g[o] / sqrtf(v[o] + EPSV);
            g_bbot[o] = b[o] - m[o] * s;
        }
    }
    {   const float *W = P.p[11], *g = P.p[12], *b = P.p[13], *m = P.p[14], *v = P.p[15];
        for (int i = tid; i < 32 * 32; i += 256) {
            int o = i >> 5;
            g_Wg1[i] = W[i] * (g[o] / sqrtf(v[o] + EPSV));
        }
        for (int o = tid; o < 32; o += 256) {
            float s = g[o] / sqrtf(v[o] + EPSV);
            g_bg1[o] = b[o] - m[o] * s;
        }
    }
    {   const float *W = P.p[16], *g = P.p[17], *b = P.p[18], *m = P.p[19], *v = P.p[20];
        for (int i = tid; i < 32 * 32; i += 256) {
            int o = i >> 5;
            g_Wg2[i] = W[i] * (g[o] / sqrtf(v[o] + EPSV));
        }
        for (int o = tid; o < 32; o += 256) {
            float s = g[o] / sqrtf(v[o] + EPSV);
            g_bg2[o] = b[o] - m[o] * s;
        }
    }
    {   const float *W = P.p[21], *g = P.p[22], *b = P.p[23], *m = P.p[24], *v = P.p[25];
        for (int i = tid; i < OUT_ * 96; i += 256) {
            int o = i / 96;
            g_Wdec[i] = W[i] * (g[o] / sqrtf(v[o] + EPSV));
        }
        for (int o = tid; o < OUT_; o += 256) {
            float s = g[o] / sqrtf(v[o] + EPSV);
            g_bdec[o] = b[o] - m[o] * s;
        }
    }
}

// ---------------- kernel 1: transpose x -> bf16 hi/lo split + sq -----------
__global__ __launch_bounds__(256) void prep_kernel(const float* __restrict__ x) {
    __shared__ float t[64][65];
    const int b = blockIdx.y, n0 = blockIdx.x * 64;
    for (int i = threadIdx.x; i < 64 * 64; i += 256) {
        int c = i >> 6, nn = i & 63;
        t[c][nn] = x[(b * C_ + c) * N_ + n0 + nn];
    }
    __syncthreads();
    for (int i = threadIdx.x; i < 64 * 64; i += 256) {
        int nn = i >> 6, c = i & 63;
        float val = t[c][nn];
        __nv_bfloat16 h = __float2bfloat16(val);
        float lo = val - __bfloat162float(h);
        size_t base = ((size_t)(b * N_ + n0 + nn)) * 128;
        g_pbf[base + c]      = h;
        g_pbf[base + 64 + c] = __float2bfloat16(lo);
    }
    if (threadIdx.x < 64) {
        float s = 0.f;
#pragma unroll
        for (int c = 0; c < 64; c++) { float v = t[c][threadIdx.x]; s += v * v; }
        g_sq[b * N_ + n0 + threadIdx.x] = s;
    }
}

// ---------------- kernel 2: res branch (-> d_out) + bottleneck (-> g_hb) ---
// 256 threads: 128 points x 2 output-halves (each thread: 64 res + 8 bot)
__global__ __launch_bounds__(256) void conv1_kernel(const float* __restrict__ x,
                                                    float* __restrict__ out) {
    __shared__ float WresS[OUT_ * C_];   // 32 KB
    __shared__ float WbotS[HB_ * C_];
    __shared__ float bresS[OUT_], bbotS[HB_];
    const int tid = threadIdx.x;
    const int b = blockIdx.y;
    const int p = tid & 127;
    const int h = tid >> 7;              // 0 or 1
    const int n = blockIdx.x * 128 + p;
    for (int i = tid; i < OUT_ * C_; i += 256) WresS[i] = g_Wres[i];
    for (int i = tid; i < HB_ * C_; i += 256)  WbotS[i] = g_Wbot[i];
    if (tid < OUT_) bresS[tid] = g_bres[tid];
    if (tid < HB_)  bbotS[tid] = g_bbot[tid];
    __syncthreads();

    float xv[64];
#pragma unroll
    for (int c = 0; c < 64; c++) xv[c] = x[(b * C_ + c) * N_ + n];

    const int oR = h * 64;
#pragma unroll 4
    for (int oo = 0; oo < 64; oo++) {
        const int o = oR + oo;
        const float4* w4 = (const float4*)(WresS + o * 64);
        float s0 = 0.f, s1 = 0.f, s2 = 0.f, s3 = 0.f;
#pragma unroll
        for (int i = 0; i < 16; i++) {
            float4 wv = w4[i];
            s0 += wv.x * xv[4 * i + 0];
            s1 += wv.y * xv[4 * i + 1];
            s2 += wv.z * xv[4 * i + 2];
            s3 += wv.w * xv[4 * i + 3];
        }
        float acc = bresS[o] + ((s0 + s1) + (s2 + s3));
        out[(b * OUT_ + o) * N_ + n] = fmaxf(acc, 0.f);
    }
    const int oB = h * 8;
#pragma unroll
    for (int oo = 0; oo < 8; oo++) {
        const int o = oB + oo;
        const float4* w4 = (const float4*)(WbotS + o * 64);
        float s0 = 0.f, s1 = 0.f, s2 = 0.f, s3 = 0.f;
#pragma unroll
        for (int i = 0; i < 16; i++) {
            float4 wv = w4[i];
            s0 += wv.x * xv[4 * i + 0];
            s1 += wv.y * xv[4 * i + 1];
            s2 += wv.z * xv[4 * i + 2];
            s3 += wv.w * xv[4 * i + 3];
        }
        float acc = bbotS[o] + ((s0 + s1) + (s2 + s3));
        g_hb[(b * N_ + n) * HB_ + o] = fmaxf(acc, 0.f);
    }
}

// ---------------- kernel 3: d2 via bf16 mma, two-pass full hi/lo product ---
constexpr int SST = 136;   // smem row stride in bf16 (272B: conflict-free ldmatrix)

__global__ __launch_bounds__(256) void d2gemm_kernel() {
    extern __shared__ __nv_bfloat16 sm[];
    __nv_bfloat16* As = sm;
    __nv_bfloat16* Bs = sm + 128 * SST;
    const int tid = threadIdx.x;
    const int lane = tid & 31, warp = tid >> 5;
    const int b = blockIdx.z;
    const int m0 = blockIdx.y * 128, n0 = blockIdx.x * 128;
    const int mBase = (warp >> 2) * 64;
    const int nBase = (warp & 3) * 32;

    {
        const uint4* srcA = (const uint4*)(g_pbf + ((size_t)(b * N_ + m0)) * 128);
        const uint4* srcB = (const uint4*)(g_pbf + ((size_t)(b * N_ + n0)) * 128);
#pragma unroll
        for (int i = tid; i < 2048; i += 256) {
            int r = i >> 4, c = i & 15;
            *(uint4*)((char*)As + r * 272 + c * 16) = srcA[i];
            *(uint4*)((char*)Bs + r * 272 + c * 16) = srcB[i];
        }
    }
    __syncthreads();

    float acc[16][4];
#pragma unroll
    for (int t = 0; t < 16; t++) { acc[t][0] = acc[t][1] = acc[t][2] = acc[t][3] = 0.f; }

    unsigned aBase = (unsigned)__cvta_generic_to_shared(As)
                   + ((mBase + (lane & 15)) * SST + ((lane >> 4) << 3)) * 2;
    unsigned bBase = (unsigned)__cvta_generic_to_shared(Bs)
                   + ((nBase + (lane & 7) + ((lane >> 4) << 3)) * SST + (((lane >> 3) & 1) << 3)) * 2;

#pragma unroll
    for (int ks = 0; ks < 8; ks++) {
        unsigned a[4][4], bf[2][4], bx[2][4];
#pragma unroll
        for (int i = 0; i < 4; i++)
            ldsm4(a[i][0], a[i][1], a[i][2], a[i][3], aBase + i * (16 * SST * 2) + ks * 32);
#pragma unroll
        for (int i = 0; i < 2; i++)
            ldsm4(bf[i][0], bf[i][1], bf[i][2], bf[i][3], bBase + i * (16 * SST * 2) + ks * 32);
#pragma unroll
        for (int i = 0; i < 2; i++)
            ldsm4(bx[i][0], bx[i][1], bx[i][2], bx[i][3],
                  bBase + i * (16 * SST * 2) + (ks ^ 4) * 32);
#pragma unroll
        for (int i = 0; i < 4; i++)
#pragma unroll
            for (int j = 0; j < 4; j++) {
                mma16816(acc[i * 4 + j], a[i],
                         bf[j >> 1][(j & 1) << 1], bf[j >> 1][((j & 1) << 1) | 1]);
                mma16816(acc[i * 4 + j], a[i],
                         bx[j >> 1][(j & 1) << 1], bx[j >> 1][((j & 1) << 1) | 1]);
            }
    }

    // epilogue: d2 = sq[m] + sq[n] - 2*dot
    const float* sqB = g_sq + b * N_;
    float sm0[4], sm1[4], sn0[4], sn1[4];
#pragma unroll
    for (int i = 0; i < 4; i++) {
        int r = m0 + mBase + i * 16 + (lane >> 2);
        sm0[i] = sqB[r]; sm1[i] = sqB[r + 8];
    }
#pragma unroll
    for (int j = 0; j < 4; j++) {
        int c = n0 + nBase + j * 8 + ((lane & 3) << 1);
        sn0[j] = sqB[c]; sn1[j] = sqB[c + 1];
    }
    float* drow = g_d2 + (size_t)b * N_ * N_;
#pragma unroll
    for (int i = 0; i < 4; i++) {
        int r0 = m0 + mBase + i * 16 + (lane >> 2);
#pragma unroll
        for (int j = 0; j < 4; j++) {
            int c = n0 + nBase + j * 8 + ((lane & 3) << 1);
            const float* t0 = acc[i * 4 + j];
            float2 v0 = make_float2(fmaf(-2.f, t0[0], sm0[i] + sn0[j]),
                                    fmaf(-2.f, t0[1], sm0[i] + sn1[j]));
            float2 v1 = make_float2(fmaf(-2.f, t0[2], sm1[i] + sn0[j]),
                                    fmaf(-2.f, t0[3], sm1[i] + sn1[j]));
            *(float2*)(drow + (size_t)r0 * N_ + c)       = v0;
            *(float2*)(drow + (size_t)(r0 + 8) * N_ + c) = v1;
        }
    }
}

// ---------------- kernel 3b: warp-per-row top-20 selection -----------------
// register-resident branchless sorted insert (compile-time indices only)
#define KNN_INSERT(dv, iv)                                                      \
    do {                                                                        \
        float _d = (dv); int _i = (iv);                                         \
        if (_d < kd[K_ - 1]) {                                                  \
            _Pragma("unroll")                                                   \
            for (int _k = K_ - 1; _k > 0; _k--) {                               \
                bool _sh = kd[_k - 1] > _d;                                     \
                bool _pl = !_sh && (kd[_k] > _d);                               \
                float _nk = _sh ? kd[_k - 1] : (_pl ? _d : kd[_k]);             \
                int   _ni = _sh ? ki[_k - 1] : (_pl ? _i : ki[_k]);             \
                kd[_k] = _nk; ki[_k] = _ni;                                     \
            }                                                                   \
            if (kd[0] > _d) { kd[0] = _d; ki[0] = _i; }                         \
        }                                                                       \
    } while (0)

__global__ __launch_bounds__(256) void knn_select_kernel() {
    __shared__ ull lists[8][32][K_];
    const int lane = threadIdx.x & 31, w = threadIdx.x >> 5;
    const int row = blockIdx.x * 8 + w;              // [0, B*N)
    const float4* dr = (const float4*)(g_d2 + (size_t)row * N_);

    float kd[K_]; int ki[K_];
#pragma unroll
    for (int k = 0; k < K_; k++) { kd[k] = 3.4e38f; ki[k] = 0x7fffffff; }

    // warp-shared threshold: warpMin(kd[19]) >= global 20th-best at all times,
    // so guarding with it (even stale) never drops a true top-20 member.
    float warpThr = 3.4e38f;

    // lane handles float4 chunks: idx = it*128 + lane*4 + c (ascending per lane)
    for (int it = 0; it < N_ / 128; it++) {
        float4 v = dr[it * 32 + lane];
        float m4 = fminf(fminf(v.x, v.y), fminf(v.z, v.w));
        if (m4 < warpThr) {                           // rare after warm-up
            int base = it * 128 + lane * 4;
            if (v.x < warpThr) KNN_INSERT(v.x, base);
            if (v.y < warpThr) KNN_INSERT(v.y, base + 1);
            if (v.z < warpThr) KNN_INSERT(v.z, base + 2);
            if (v.w < warpThr) KNN_INSERT(v.w, base + 3);
        }
        if ((it & 3) == 3) {                          // refresh threshold
            float t = kd[K_ - 1];
#pragma unroll
            for (int o = 16; o; o >>= 1)
                t = fminf(t, __shfl_xor_sync(0xffffffffu, t, o));
            warpThr = t;
        }
    }

    // pack (monotone d bits, idx) for lexicographic u64 min
#pragma unroll
    for (int k = 0; k < K_; k++) {
        unsigned ub = __float_as_uint(kd[k]);
        ub = (ub & 0x80000000u) ? ~ub : (ub | 0x80000000u);
        lists[w][lane][k] = ((ull)ub << 32) | (unsigned)ki[k];
    }
    __syncwarp();

    int pos = 0;
    ull v = lists[w][lane][0];
    int* op = g_idx + row * K_;
#pragma unroll
    for (int k = 0; k < K_; k++) {
        ull m = v;
#pragma unroll
        for (int o = 16; o; o >>= 1) {
            ull t = __shfl_xor_sync(0xffffffffu, m, o);
            m = t < m ? t : m;
        }
        if (lane == 0) op[k] = (int)(unsigned)(m & 0xffffffffu);
        if (v == m) {                                 // unique idx -> exactly one owner
            pos++;
            v = (pos < K_) ? lists[w][lane][pos] : ~0ull;
        }
    }
}

// ---------------- kernel 4: fused GCN (gather, g1, g2, gmax, decode) -------
__device__ __forceinline__ float dot16(const float* wv,
                                       float4 v0, float4 v1, float4 v2, float4 v3) {
    return wv[0] * v0.x + wv[1] * v0.y + wv[2]  * v0.z + wv[3]  * v0.w
         + wv[4] * v1.x + wv[5] * v1.y + wv[6]  * v1.z + wv[7]  * v1.w
         + wv[8] * v2.x + wv[9] * v2.y + wv[10] * v2.z + wv[11] * v2.w
         + wv[12]* v3.x + wv[13]* v3.y + wv[14] * v3.z + wv[15] * v3.w;
}

constexpr int WPB = 8;       // warps (points) per block
constexpr int WD_PAD = 100;  // padded row stride for Wdec (conflict-free float4)

__global__ __launch_bounds__(256) void gcn_kernel(float* __restrict__ out) {
    extern __shared__ float WdP[];              // [128][100] padded decode weights
    __shared__ float nbS[WPB][K_][HB_];
    __shared__ float ctrS[WPB][HB_];
    __shared__ float allfS[WPB][96];
    __shared__ int   idxS[WPB][K_];

    const int tid = threadIdx.x;
    const int w = tid >> 5, lane = tid & 31;
    const int b = blockIdx.y;
    const int n = blockIdx.x * WPB + w;

    for (int i = tid; i < OUT_ * 96; i += 256) {
        int o = i / 96, c = i - o * 96;
        WdP[o * WD_PAD + c] = g_Wdec[i];
    }

    float w1[32], w2[32];
#pragma unroll
    for (int c = 0; c < 32; c++) { w1[c] = g_Wg1[lane * 32 + c]; w2[c] = g_Wg2[lane * 32 + c]; }
    const float b1 = g_bg1[lane], b2 = g_bg2[lane];

    if (lane < K_)  idxS[w][lane] = g_idx[(b * N_ + n) * K_ + lane];
    if (lane < HB_) ctrS[w][lane] = g_hb[(b * N_ + n) * HB_ + lane];
    __syncwarp();

    for (int t = lane; t < K_ * HB_; t += 32) {
        int k = t >> 4, c = t & 15;
        nbS[w][k][c] = g_hb[(b * N_ + idxS[w][k]) * HB_ + c];
    }
    __syncthreads();   // also covers WdP load

    float pre1 = b1, pre2 = b2;
#pragma unroll
    for (int c = 0; c < 16; c++) {
        float cv = ctrS[w][c];
        pre1 += w1[16 + c] * cv;
        pre2 += w2[16 + c] * cv;
    }

    float acc1 = -3.4e38f, acc2 = -3.4e38f;
#pragma unroll
    for (int k = 0; k < K_; k++) {
        const float4* nb4 = (const float4*)nbS[w][k];
        float4 v0 = nb4[0], v1 = nb4[1], v2 = nb4[2], v3 = nb4[3];
        float y = pre1 + dot16(w1, v0, v1, v2, v3);
        float ly = y > 0.f ? y : 0.2f * y;
        acc1 = fmaxf(acc1, ly);
        if ((k & 1) == 0) {
            float y2 = pre2 + dot16(w2, v0, v1, v2, v3);
            float ly2 = y2 > 0.f ? y2 : 0.2f * y2;
            acc2 = fmaxf(acc2, ly2);
        }
    }

    float gm = -3.4e38f;
    if (lane < 16) {
#pragma unroll
        for (int k = 0; k < K_; k++) gm = fmaxf(gm, nbS[w][k][lane]);
    }
    allfS[w][lane]      = acc1;
    allfS[w][32 + lane] = acc2;
    allfS[w][64 + lane] = (lane < 16) ? gm : ctrS[w][lane - 16];
    __syncwarp();

    float accd0 = g_bdec[lane],      accd1 = g_bdec[lane + 32];
    float accd2 = g_bdec[lane + 64], accd3 = g_bdec[lane + 96];
    const float4* af4 = (const float4*)allfS[w];
    const float4* wr0 = (const float4*)(WdP + (lane)      * WD_PAD);
    const float4* wr1 = (const float4*)(WdP + (lane + 32) * WD_PAD);
    const float4* wr2 = (const float4*)(WdP + (lane + 64) * WD_PAD);
    const float4* wr3 = (const float4*)(WdP + (lane + 96) * WD_PAD);
#pragma unroll
    for (int c4 = 0; c4 < 24; c4++) {
        float4 a = af4[c4];
        float4 q0 = wr0[c4]; accd0 += q0.x*a.x + q0.y*a.y + q0.z*a.z + q0.w*a.w;
        float4 q1 = wr1[c4]; accd1 += q1.x*a.x + q1.y*a.y + q1.z*a.z + q1.w*a.w;
        float4 q2 = wr2[c4]; accd2 += q2.x*a.x + q2.y*a.y + q2.z*a.z + q2.w*a.w;
        float4 q3 = wr3[c4]; accd3 += q3.x*a.x + q3.y*a.y + q3.z*a.z + q3.w*a.w;
    }
    {
        int i0 = (b * OUT_ + lane)      * N_ + n;
        int i1 = (b * OUT_ + lane + 32) * N_ + n;
        int i2 = (b * OUT_ + lane + 64) * N_ + n;
        int i3 = (b * OUT_ + lane + 96) * N_ + n;
        float r0 = out[i0], r1 = out[i1], r2 = out[i2], r3 = out[i3];
        out[i0] = fmaxf(accd0, 0.f) + r0;
        out[i1] = fmaxf(accd1, 0.f) + r1;
        out[i2] = fmaxf(accd2, 0.f) + r2;
        out[i3] = fmaxf(accd3, 0.f) + r3;
    }
}

// ---------------- launch ---------------------------------------------------
extern "C" void kernel_launch(void* const* d_in, const int* in_sizes, int n_in,
                              void* d_out, int out_size) {
    Params P;
    for (int i = 0; i < 26; i++) P.p[i] = (const float*)d_in[i];
    const float* x = P.p[0];
    float* out = (float*)d_out;

    const int gemm_smem = 2 * 128 * SST * (int)sizeof(__nv_bfloat16);   // 69632 B
    cudaFuncSetAttribute(d2gemm_kernel, cudaFuncAttributeMaxDynamicSharedMemorySize, gemm_smem);
    cudaFuncSetAttribute(gcn_kernel, cudaFuncAttributeMaxDynamicSharedMemorySize,
                         OUT_ * WD_PAD * (int)sizeof(float));

    fold_kernel<<<1, 256>>>(P);
    prep_kernel<<<dim3(N_ / 64, B_), 256>>>(x);
    conv1_kernel<<<dim3(N_ / 128, B_), 256>>>(x, out);
    d2gemm_kernel<<<dim3(N_ / 128, N_ / 128, B_), 256, gemm_smem>>>();
    knn_select_kernel<<<(B_ * N_) / 8, 256>>>();
    gcn_kernel<<<dim3(N_ / WPB, B_), 256, OUT_ * WD_PAD * (int)sizeof(float)>>>(out);
}

// round 11
// speedup vs baseline: 1.6011x; 1.6011x over previous
#include <cuda_runtime.h>
#include <cuda_bf16.h>
#include <math.h>

#define EPSV 1e-5f
constexpr int B_ = 4, C_ = 64, N_ = 4096, OUT_ = 128, K_ = 20;
constexpr int HB_ = 16;   // C/4

typedef unsigned long long ull;

// ---------------- scratch (device globals; no allocation allowed) ----------
__device__ __align__(16) __nv_bfloat16 g_pbf[B_ * N_ * 128];  // [B][N][hi64|lo64]
__device__ float g_sq [B_ * N_];                  // squared norms (exact fp32)
__device__ float g_hb [B_ * N_ * HB_];            // bottleneck features [B][N][16]
__device__ int   g_idx[B_ * N_ * K_];             // knn indices
__device__ float g_d2 [(size_t)B_ * N_ * N_];     // 268MB distance matrix
__device__ float g_Wres[OUT_ * C_], g_bres[OUT_];
__device__ float g_Wbot[HB_ * C_],  g_bbot[HB_];
__device__ float g_Wg1[32 * 32],    g_bg1[32];
__device__ float g_Wg2[32 * 32],    g_bg2[32];
__device__ float g_Wdec[OUT_ * 96], g_bdec[OUT_];

struct Params { const float* p[26]; };

// ---------------- mma helpers ----------------------------------------------
__device__ __forceinline__ void ldsm4(unsigned& r0, unsigned& r1, unsigned& r2, unsigned& r3,
                                      unsigned addr) {
    asm volatile("ldmatrix.sync.aligned.m8n8.x4.shared.b16 {%0,%1,%2,%3}, [%4];"
                 : "=r"(r0), "=r"(r1), "=r"(r2), "=r"(r3) : "r"(addr));
}
__device__ __forceinline__ void mma16816(float* c, const unsigned* a, unsigned b0, unsigned b1) {
    asm volatile("mma.sync.aligned.m16n8k16.row.col.f32.bf16.bf16.f32 "
                 "{%0,%1,%2,%3}, {%4,%5,%6,%7}, {%8,%9}, {%0,%1,%2,%3};"
                 : "+f"(c[0]), "+f"(c[1]), "+f"(c[2]), "+f"(c[3])
                 : "r"(a[0]), "r"(a[1]), "r"(a[2]), "r"(a[3]), "r"(b0), "r"(b1));
}

// ---------------- kernel 0: fold BN into conv weights ----------------------
__global__ void fold_kernel(Params P) {
    const int tid = threadIdx.x;
    {   const float *W = P.p[1], *g = P.p[2], *b = P.p[3], *m = P.p[4], *v = P.p[5];
        for (int i = tid; i < OUT_ * C_; i += 256) {
            int o = i >> 6;
            g_Wres[i] = W[i] * (g[o] / sqrtf(v[o] + EPSV));
        }
        for (int o = tid; o < OUT_; o += 256) {
            float s = g[o] / sqrtf(v[o] + EPSV);
            g_bres[o] = b[o] - m[o] * s;
        }
    }
    {   const float *W = P.p[6], *g = P.p[7], *b = P.p[8], *m = P.p[9], *v = P.p[10];
        for (int i = tid; i < HB_ * C_; i += 256) {
            int o = i >> 6;
            g_Wbot[i] = W[i] * (g[o] / sqrtf(v[o] + EPSV));
        }
        for (int o = tid; o < HB_; o += 256) {
            float s = g[o] / sqrtf(v[o] + EPSV);
            g_bbot[o] = b[o] - m[o] * s;
        }
    }
    {   const float *W = P.p[11], *g = P.p[12], *b = P.p[13], *m = P.p[14], *v = P.p[15];
        for (int i = tid; i < 32 * 32; i += 256) {
            int o = i >> 5;
            g_Wg1[i] = W[i] * (g[o] / sqrtf(v[o] + EPSV));
        }
        for (int o = tid; o < 32; o += 256) {
            float s = g[o] / sqrtf(v[o] + EPSV);
            g_bg1[o] = b[o] - m[o] * s;
        }
    }
    {   const float *W = P.p[16], *g = P.p[17], *b = P.p[18], *m = P.p[19], *v = P.p[20];
        for (int i = tid; i < 32 * 32; i += 256) {
            int o = i >> 5;
            g_Wg2[i] = W[i] * (g[o] / sqrtf(v[o] + EPSV));
        }
        for (int o = tid; o < 32; o += 256) {
            float s = g[o] / sqrtf(v[o] + EPSV);
            g_bg2[o] = b[o] - m[o] * s;
        }
    }
    {   const float *W = P.p[21], *g = P.p[22], *b = P.p[23], *m = P.p[24], *v = P.p[25];
        for (int i = tid; i < OUT_ * 96; i += 256) {
            int o = i / 96;
            g_Wdec[i] = W[i] * (g[o] / sqrtf(v[o] + EPSV));
        }
        for (int o = tid; o < OUT_; o += 256) {
            float s = g[o] / sqrtf(v[o] + EPSV);
            g_bdec[o] = b[o] - m[o] * s;
        }
    }
}

// ---------------- kernel 1: transpose x -> bf16 hi/lo split + sq -----------
__global__ __launch_bounds__(256) void prep_kernel(const float* __restrict__ x) {
    __shared__ float t[64][65];
    const int b = blockIdx.y, n0 = blockIdx.x * 64;
    for (int i = threadIdx.x; i < 64 * 64; i += 256) {
        int c = i >> 6, nn = i & 63;
        t[c][nn] = x[(b * C_ + c) * N_ + n0 + nn];
    }
    __syncthreads();
    for (int i = threadIdx.x; i < 64 * 64; i += 256) {
        int nn = i >> 6, c = i & 63;
        float val = t[c][nn];
        __nv_bfloat16 h = __float2bfloat16(val);
        float lo = val - __bfloat162float(h);
        size_t base = ((size_t)(b * N_ + n0 + nn)) * 128;
        g_pbf[base + c]      = h;
        g_pbf[base + 64 + c] = __float2bfloat16(lo);
    }
    if (threadIdx.x < 64) {
        float s = 0.f;
#pragma unroll
        for (int c = 0; c < 64; c++) { float v = t[c][threadIdx.x]; s += v * v; }
        g_sq[b * N_ + n0 + threadIdx.x] = s;
    }
}

// ---------------- kernel 2: res branch (-> d_out) + bottleneck (-> g_hb) ---
// 256 threads: 128 points x 2 output-halves (each thread: 64 res + 8 bot)
__global__ __launch_bounds__(256) void conv1_kernel(const float* __restrict__ x,
                                                    float* __restrict__ out) {
    __shared__ float WresS[OUT_ * C_];   // 32 KB
    __shared__ float WbotS[HB_ * C_];
    __shared__ float bresS[OUT_], bbotS[HB_];
    const int tid = threadIdx.x;
    const int b = blockIdx.y;
    const int p = tid & 127;
    const int h = tid >> 7;              // 0 or 1
    const int n = blockIdx.x * 128 + p;
    for (int i = tid; i < OUT_ * C_; i += 256) WresS[i] = g_Wres[i];
    for (int i = tid; i < HB_ * C_; i += 256)  WbotS[i] = g_Wbot[i];
    if (tid < OUT_) bresS[tid] = g_bres[tid];
    if (tid < HB_)  bbotS[tid] = g_bbot[tid];
    __syncthreads();

    float xv[64];
#pragma unroll
    for (int c = 0; c < 64; c++) xv[c] = x[(b * C_ + c) * N_ + n];

    const int oR = h * 64;
#pragma unroll 4
    for (int oo = 0; oo < 64; oo++) {
        const int o = oR + oo;
        const float4* w4 = (const float4*)(WresS + o * 64);
        float s0 = 0.f, s1 = 0.f, s2 = 0.f, s3 = 0.f;
#pragma unroll
        for (int i = 0; i < 16; i++) {
            float4 wv = w4[i];
            s0 += wv.x * xv[4 * i + 0];
            s1 += wv.y * xv[4 * i + 1];
            s2 += wv.z * xv[4 * i + 2];
            s3 += wv.w * xv[4 * i + 3];
        }
        float acc = bresS[o] + ((s0 + s1) + (s2 + s3));
        out[(b * OUT_ + o) * N_ + n] = fmaxf(acc, 0.f);
    }
    const int oB = h * 8;
#pragma unroll
    for (int oo = 0; oo < 8; oo++) {
        const int o = oB + oo;
        const float4* w4 = (const float4*)(WbotS + o * 64);
        float s0 = 0.f, s1 = 0.f, s2 = 0.f, s3 = 0.f;
#pragma unroll
        for (int i = 0; i < 16; i++) {
            float4 wv = w4[i];
            s0 += wv.x * xv[4 * i + 0];
            s1 += wv.y * xv[4 * i + 1];
            s2 += wv.z * xv[4 * i + 2];
            s3 += wv.w * xv[4 * i + 3];
        }
        float acc = bbotS[o] + ((s0 + s1) + (s2 + s3));
        g_hb[(b * N_ + n) * HB_ + o] = fmaxf(acc, 0.f);
    }
}

// ---------------- kernel 3: d2 via bf16 mma, two-pass full hi/lo product ---
constexpr int SST = 136;   // smem row stride in bf16 (272B: conflict-free ldmatrix)

__global__ __launch_bounds__(256) void d2gemm_kernel() {
    extern __shared__ __nv_bfloat16 sm[];
    __nv_bfloat16* As = sm;
    __nv_bfloat16* Bs = sm + 128 * SST;
    const int tid = threadIdx.x;
    const int lane = tid & 31, warp = tid >> 5;
    const int b = blockIdx.z;
    const int m0 = blockIdx.y * 128, n0 = blockIdx.x * 128;
    const int mBase = (warp >> 2) * 64;
    const int nBase = (warp & 3) * 32;

    {
        const uint4* srcA = (const uint4*)(g_pbf + ((size_t)(b * N_ + m0)) * 128);
        const uint4* srcB = (const uint4*)(g_pbf + ((size_t)(b * N_ + n0)) * 128);
#pragma unroll
        for (int i = tid; i < 2048; i += 256) {
            int r = i >> 4, c = i & 15;
            *(uint4*)((char*)As + r * 272 + c * 16) = srcA[i];
            *(uint4*)((char*)Bs + r * 272 + c * 16) = srcB[i];
        }
    }
    __syncthreads();

    float acc[16][4];
#pragma unroll
    for (int t = 0; t < 16; t++) { acc[t][0] = acc[t][1] = acc[t][2] = acc[t][3] = 0.f; }

    unsigned aBase = (unsigned)__cvta_generic_to_shared(As)
                   + ((mBase + (lane & 15)) * SST + ((lane >> 4) << 3)) * 2;
    unsigned bBase = (unsigned)__cvta_generic_to_shared(Bs)
                   + ((nBase + (lane & 7) + ((lane >> 4) << 3)) * SST + (((lane >> 3) & 1) << 3)) * 2;

#pragma unroll
    for (int ks = 0; ks < 8; ks++) {
        unsigned a[4][4], bf[2][4], bx[2][4];
#pragma unroll
        for (int i = 0; i < 4; i++)
            ldsm4(a[i][0], a[i][1], a[i][2], a[i][3], aBase + i * (16 * SST * 2) + ks * 32);
#pragma unroll
        for (int i = 0; i < 2; i++)
            ldsm4(bf[i][0], bf[i][1], bf[i][2], bf[i][3], bBase + i * (16 * SST * 2) + ks * 32);
#pragma unroll
        for (int i = 0; i < 2; i++)
            ldsm4(bx[i][0], bx[i][1], bx[i][2], bx[i][3],
                  bBase + i * (16 * SST * 2) + (ks ^ 4) * 32);
#pragma unroll
        for (int i = 0; i < 4; i++)
#pragma unroll
            for (int j = 0; j < 4; j++) {
                mma16816(acc[i * 4 + j], a[i],
                         bf[j >> 1][(j & 1) << 1], bf[j >> 1][((j & 1) << 1) | 1]);
                mma16816(acc[i * 4 + j], a[i],
                         bx[j >> 1][(j & 1) << 1], bx[j >> 1][((j & 1) << 1) | 1]);
            }
    }

    // epilogue: d2 = sq[m] + sq[n] - 2*dot
    const float* sqB = g_sq + b * N_;
    float sm0[4], sm1[4], sn0[4], sn1[4];
#pragma unroll
    for (int i = 0; i < 4; i++) {
        int r = m0 + mBase + i * 16 + (lane >> 2);
        sm0[i] = sqB[r]; sm1[i] = sqB[r + 8];
    }
#pragma unroll
    for (int j = 0; j < 4; j++) {
        int c = n0 + nBase + j * 8 + ((lane & 3) << 1);
        sn0[j] = sqB[c]; sn1[j] = sqB[c + 1];
    }
    float* drow = g_d2 + (size_t)b * N_ * N_;
#pragma unroll
    for (int i = 0; i < 4; i++) {
        int r0 = m0 + mBase + i * 16 + (lane >> 2);
#pragma unroll
        for (int j = 0; j < 4; j++) {
            int c = n0 + nBase + j * 8 + ((lane & 3) << 1);
            const float* t0 = acc[i * 4 + j];
            float2 v0 = make_float2(fmaf(-2.f, t0[0], sm0[i] + sn0[j]),
                                    fmaf(-2.f, t0[1], sm0[i] + sn1[j]));
            float2 v1 = make_float2(fmaf(-2.f, t0[2], sm1[i] + sn0[j]),
                                    fmaf(-2.f, t0[3], sm1[i] + sn1[j]));
            *(float2*)(drow + (size_t)r0 * N_ + c)       = v0;
            *(float2*)(drow + (size_t)(r0 + 8) * N_ + c) = v1;
        }
    }
}

// ---------------- kernel 3b: warp-collective top-20 selection --------------
// ONE sorted-by-(d,idx) list per warp, one slot per lane (slots 0..31 ascending,
// only 0..19 are the answer). Ballot finds candidates vs thr=slot[19]; each
// insertion is a warp-parallel shfl-up shift. ~126 true insertions per row.
__global__ __launch_bounds__(256) void knn_select_kernel() {
    const int lane = threadIdx.x & 31, w = threadIdx.x >> 5;
    const int row = blockIdx.x * 8 + w;              // [0, B*N)
    const float4* dr = (const float4*)(g_d2 + (size_t)row * N_);

    float sd = 3.4e38f;        // this lane's list slot (distance)
    int   si = 0x7fffffff;     // this lane's list slot (index)
    float thrF = 3.4e38f;      // slot[19] distance, replicated

    for (int it = 0; it < N_ / 128; it++) {
        float4 v = dr[it * 32 + lane];
        float m4 = fminf(fminf(v.x, v.y), fminf(v.z, v.w));
        if (!__ballot_sync(0xffffffffu, m4 <= thrF)) continue;
        const int base = it * 128 + lane * 4;
#pragma unroll
        for (int c = 0; c < 4; c++) {
            float d = (c == 0) ? v.x : (c == 1) ? v.y : (c == 2) ? v.z : v.w;
            int idx = base + c;
            unsigned ball = __ballot_sync(0xffffffffu, d <= thrF);
            while (ball) {
                int src = __ffs(ball) - 1;
                float nd = __shfl_sync(0xffffffffu, d, src);
                int   ni = __shfl_sync(0xffffffffu, idx, src);
                // warp-collective sorted insert of (nd, ni)
                bool pred = (sd > nd) || (sd == nd && si > ni);
                unsigned pb = __ballot_sync(0xffffffffu, pred);
                if (pb) {
                    int p = __ffs(pb) - 1;
                    float shd = __shfl_up_sync(0xffffffffu, sd, 1);
                    int   shi = __shfl_up_sync(0xffffffffu, si, 1);
                    if (lane > p)  { sd = shd; si = shi; }
                    if (lane == p) { sd = nd;  si = ni;  }
                    thrF = __shfl_sync(0xffffffffu, sd, 19);
                }
                ball &= ~(1u << src);
                ball &= __ballot_sync(0xffffffffu, d <= thrF);   // re-check vs tightened thr
            }
        }
    }
    if (lane < K_) g_idx[row * K_ + lane] = si;      // slots 0..19 = exact sorted top-20
}

// ---------------- kernel 4: fused GCN (gather, g1, g2, gmax, decode) -------
__device__ __forceinline__ float dot16(const float* wv,
                                       float4 v0, float4 v1, float4 v2, float4 v3) {
    return wv[0] * v0.x + wv[1] * v0.y + wv[2]  * v0.z + wv[3]  * v0.w
         + wv[4] * v1.x + wv[5] * v1.y + wv[6]  * v1.z + wv[7]  * v1.w
         + wv[8] * v2.x + wv[9] * v2.y + wv[10] * v2.z + wv[11] * v2.w
         + wv[12]* v3.x + wv[13]* v3.y + wv[14] * v3.z + wv[15] * v3.w;
}

constexpr int WPB = 8;       // warps (points) per block
constexpr int WD_PAD = 100;  // padded row stride for Wdec (conflict-free float4)

__global__ __launch_bounds__(256) void gcn_kernel(float* __restrict__ out) {
    extern __shared__ float WdP[];              // [128][100] padded decode weights
    __shared__ float nbS[WPB][K_][HB_];
    __shared__ float ctrS[WPB][HB_];
    __shared__ float allfS[WPB][96];
    __shared__ int   idxS[WPB][K_];

    const int tid = threadIdx.x;
    const int w = tid >> 5, lane = tid & 31;
    const int b = blockIdx.y;
    const int n = blockIdx.x * WPB + w;

    for (int i = tid; i < OUT_ * 96; i += 256) {
        int o = i / 96, c = i - o * 96;
        WdP[o * WD_PAD + c] = g_Wdec[i];
    }

    float w1[32], w2[32];
#pragma unroll
    for (int c = 0; c < 32; c++) { w1[c] = g_Wg1[lane * 32 + c]; w2[c] = g_Wg2[lane * 32 + c]; }
    const float b1 = g_bg1[lane], b2 = g_bg2[lane];

    if (lane < K_)  idxS[w][lane] = g_idx[(b * N_ + n) * K_ + lane];
    if (lane < HB_) ctrS[w][lane] = g_hb[(b * N_ + n) * HB_ + lane];
    __syncwarp();

    for (int t = lane; t < K_ * HB_; t += 32) {
        int k = t >> 4, c = t & 15;
        nbS[w][k][c] = g_hb[(b * N_ + idxS[w][k]) * HB_ + c];
    }
    __syncthreads();   // also covers WdP load

    float pre1 = b1, pre2 = b2;
#pragma unroll
    for (int c = 0; c < 16; c++) {
        float cv = ctrS[w][c];
        pre1 += w1[16 + c] * cv;
        pre2 += w2[16 + c] * cv;
    }

    float acc1 = -3.4e38f, acc2 = -3.4e38f;
#pragma unroll
    for (int k = 0; k < K_; k++) {
        const float4* nb4 = (const float4*)nbS[w][k];
        float4 v0 = nb4[0], v1 = nb4[1], v2 = nb4[2], v3 = nb4[3];
        float y = pre1 + dot16(w1, v0, v1, v2, v3);
        float ly = y > 0.f ? y : 0.2f * y;
        acc1 = fmaxf(acc1, ly);
        if ((k & 1) == 0) {
            float y2 = pre2 + dot16(w2, v0, v1, v2, v3);
            float ly2 = y2 > 0.f ? y2 : 0.2f * y2;
            acc2 = fmaxf(acc2, ly2);
        }
    }

    float gm = -3.4e38f;
    if (lane < 16) {
#pragma unroll
        for (int k = 0; k < K_; k++) gm = fmaxf(gm, nbS[w][k][lane]);
    }
    allfS[w][lane]      = acc1;
    allfS[w][32 + lane] = acc2;
    allfS[w][64 + lane] = (lane < 16) ? gm : ctrS[w][lane - 16];
    __syncwarp();

    float accd0 = g_bdec[lane],      accd1 = g_bdec[lane + 32];
    float accd2 = g_bdec[lane + 64], accd3 = g_bdec[lane + 96];
    const float4* af4 = (const float4*)allfS[w];
    const float4* wr0 = (const float4*)(WdP + (lane)      * WD_PAD);
    const float4* wr1 = (const float4*)(WdP + (lane + 32) * WD_PAD);
    const float4* wr2 = (const float4*)(WdP + (lane + 64) * WD_PAD);
    const float4* wr3 = (const float4*)(WdP + (lane + 96) * WD_PAD);
#pragma unroll
    for (int c4 = 0; c4 < 24; c4++) {
        float4 a = af4[c4];
        float4 q0 = wr0[c4]; accd0 += q0.x*a.x + q0.y*a.y + q0.z*a.z + q0.w*a.w;
        float4 q1 = wr1[c4]; accd1 += q1.x*a.x + q1.y*a.y + q1.z*a.z + q1.w*a.w;
        float4 q2 = wr2[c4]; accd2 += q2.x*a.x + q2.y*a.y + q2.z*a.z + q2.w*a.w;
        float4 q3 = wr3[c4]; accd3 += q3.x*a.x + q3.y*a.y + q3.z*a.z + q3.w*a.w;
    }
    {
        int i0 = (b * OUT_ + lane)      * N_ + n;
        int i1 = (b * OUT_ + lane + 32) * N_ + n;
        int i2 = (b * OUT_ + lane + 64) * N_ + n;
        int i3 = (b * OUT_ + lane + 96) * N_ + n;
        float r0 = out[i0], r1 = out[i1], r2 = out[i2], r3 = out[i3];
        out[i0] = fmaxf(accd0, 0.f) + r0;
        out[i1] = fmaxf(accd1, 0.f) + r1;
        out[i2] = fmaxf(accd2, 0.f) + r2;
        out[i3] = fmaxf(accd3, 0.f) + r3;
    }
}

// ---------------- launch ---------------------------------------------------
extern "C" void kernel_launch(void* const* d_in, const int* in_sizes, int n_in,
                              void* d_out, int out_size) {
    Params P;
    for (int i = 0; i < 26; i++) P.p[i] = (const float*)d_in[i];
    const float* x = P.p[0];
    float* out = (float*)d_out;

    const int gemm_smem = 2 * 128 * SST * (int)sizeof(__nv_bfloat16);   // 69632 B
    cudaFuncSetAttribute(d2gemm_kernel, cudaFuncAttributeMaxDynamicSharedMemorySize, gemm_smem);
    cudaFuncSetAttribute(gcn_kernel, cudaFuncAttributeMaxDynamicSharedMemorySize,
                         OUT_ * WD_PAD * (int)sizeof(float));

    fold_kernel<<<1, 256>>>(P);
    prep_kernel<<<dim3(N_ / 64, B_), 256>>>(x);
    conv1_kernel<<<dim3(N_ / 128, B_), 256>>>(x, out);
    d2gemm_kernel<<<dim3(N_ / 128, N_ / 128, B_), 256, gemm_smem>>>();
    knn_select_kernel<<<(B_ * N_) / 8, 256>>>();
    gcn_kernel<<<dim3(N_ / WPB, B_), 256, OUT_ * WD_PAD * (int)sizeof(float)>>>(out);
}

// round 16
// speedup vs baseline: 1.8974x; 1.1851x over previous
#include <cuda_runtime.h>
#include <cuda_bf16.h>
#include <math.h>

#define EPSV 1e-5f
constexpr int B_ = 4, C_ = 64, N_ = 4096, OUT_ = 128, K_ = 20;
constexpr int HB_ = 16;   // C/4

typedef unsigned long long ull;

// ---------------- scratch (device globals; no allocation allowed) ----------
__device__ __align__(16) __nv_bfloat16 g_pbf[B_ * N_ * 128];  // [B][N][hi64|lo64]
__device__ float g_sq [B_ * N_];                  // squared norms (exact fp32)
__device__ float g_hb [B_ * N_ * HB_];            // bottleneck features [B][N][16]
__device__ int   g_idx[B_ * N_ * K_];             // knn indices
__device__ float g_d2 [(size_t)B_ * N_ * N_];     // 268MB distance matrix
__device__ __align__(16) float g_Wres[OUT_ * C_];
__device__ float g_bres[OUT_];
__device__ __align__(16) float g_Wbot[HB_ * C_];
__device__ float g_bbot[HB_];
__device__ __align__(16) float g_Wg1[32 * 32];
__device__ float g_bg1[32];
__device__ __align__(16) float g_Wg2[32 * 32];
__device__ float g_bg2[32];
__device__ __align__(16) float g_Wdec[OUT_ * 96];
__device__ float g_bdec[OUT_];

struct Params { const float* p[26]; };

// ---------------- mma helpers ----------------------------------------------
__device__ __forceinline__ void ldsm4(unsigned& r0, unsigned& r1, unsigned& r2, unsigned& r3,
                                      unsigned addr) {
    asm volatile("ldmatrix.sync.aligned.m8n8.x4.shared.b16 {%0,%1,%2,%3}, [%4];"
                 : "=r"(r0), "=r"(r1), "=r"(r2), "=r"(r3) : "r"(addr));
}
__device__ __forceinline__ void mma16816(float* c, const unsigned* a, unsigned b0, unsigned b1) {
    asm volatile("mma.sync.aligned.m16n8k16.row.col.f32.bf16.bf16.f32 "
                 "{%0,%1,%2,%3}, {%4,%5,%6,%7}, {%8,%9}, {%0,%1,%2,%3};"
                 : "+f"(c[0]), "+f"(c[1]), "+f"(c[2]), "+f"(c[3])
                 : "r"(a[0]), "r"(a[1]), "r"(a[2]), "r"(a[3]), "r"(b0), "r"(b1));
}

// ---------------- kernel 0: fold BN into conv weights ----------------------
__global__ void fold_kernel(Params P) {
    const int tid = threadIdx.x;
    {   const float *W = P.p[1], *g = P.p[2], *b = P.p[3], *m = P.p[4], *v = P.p[5];
        for (int i = tid; i < OUT_ * C_; i += 256) {
            int o = i >> 6;
            g_Wres[i] = W[i] * (g[o] / sqrtf(v[o] + EPSV));
        }
        for (int o = tid; o < OUT_; o += 256) {
            float s = g[o] / sqrtf(v[o] + EPSV);
            g_bres[o] = b[o] - m[o] * s;
        }
    }
    {   const float *W = P.p[6], *g = P.p[7], *b = P.p[8], *m = P.p[9], *v = P.p[10];
        for (int i = tid; i < HB_ * C_; i += 256) {
            int o = i >> 6;
            g_Wbot[i] = W[i] * (g[o] / sqrtf(v[o] + EPSV));
        }
        for (int o = tid; o < HB_; o += 256) {
            float s = g[o] / sqrtf(v[o] + EPSV);
            g_bbot[o] = b[o] - m[o] * s;
        }
    }
    {   const float *W = P.p[11], *g = P.p[12], *b = P.p[13], *m = P.p[14], *v = P.p[15];
        for (int i = tid; i < 32 * 32; i += 256) {
            int o = i >> 5;
            g_Wg1[i] = W[i] * (g[o] / sqrtf(v[o] + EPSV));
        }
        for (int o = tid; o < 32; o += 256) {
            float s = g[o] / sqrtf(v[o] + EPSV);
            g_bg1[o] = b[o] - m[o] * s;
        }
    }
    {   const float *W = P.p[16], *g = P.p[17], *b = P.p[18], *m = P.p[19], *v = P.p[20];
        for (int i = tid; i < 32 * 32; i += 256) {
            int o = i >> 5;
            g_Wg2[i] = W[i] * (g[o] / sqrtf(v[o] + EPSV));
        }
        for (int o = tid; o < 32; o += 256) {
            float s = g[o] / sqrtf(v[o] + EPSV);
            g_bg2[o] = b[o] - m[o] * s;
        }
    }
    {   const float *W = P.p[21], *g = P.p[22], *b = P.p[23], *m = P.p[24], *v = P.p[25];
        for (int i = tid; i < OUT_ * 96; i += 256) {
            int o = i / 96;
            g_Wdec[i] = W[i] * (g[o] / sqrtf(v[o] + EPSV));
        }
        for (int o = tid; o < OUT_; o += 256) {
            float s = g[o] / sqrtf(v[o] + EPSV);
            g_bdec[o] = b[o] - m[o] * s;
        }
    }
}

// ---------------- kernel 1: transpose x -> bf16 hi/lo split + sq -----------
__global__ __launch_bounds__(256) void prep_kernel(const float* __restrict__ x) {
    __shared__ float t[64][65];
    const int b = blockIdx.y, n0 = blockIdx.x * 64;
    for (int i = threadIdx.x; i < 64 * 64; i += 256) {
        int c = i >> 6, nn = i & 63;
        t[c][nn] = x[(b * C_ + c) * N_ + n0 + nn];
    }
    __syncthreads();
    for (int i = threadIdx.x; i < 64 * 64; i += 256) {
        int nn = i >> 6, c = i & 63;
        float val = t[c][nn];
        __nv_bfloat16 h = __float2bfloat16(val);
        float lo = val - __bfloat162float(h);
        size_t base = ((size_t)(b * N_ + n0 + nn)) * 128;
        g_pbf[base + c]      = h;
        g_pbf[base + 64 + c] = __float2bfloat16(lo);
    }
    if (threadIdx.x < 64) {
        float s = 0.f;
#pragma unroll
        for (int c = 0; c < 64; c++) { float v = t[c][threadIdx.x]; s += v * v; }
        g_sq[b * N_ + n0 + threadIdx.x] = s;
    }
}

// ---------------- kernel 2: res branch (-> d_out) + bottleneck (-> g_hb) ---
// 256 threads: 64 points x 4 output-groups (each thread: 32 res + 4 bot)
__global__ __launch_bounds__(256) void conv1_kernel(const float* __restrict__ x,
                                                    float* __restrict__ out) {
    __shared__ float WresS[OUT_ * C_];   // 32 KB
    __shared__ float WbotS[HB_ * C_];
    __shared__ float bresS[OUT_], bbotS[HB_];
    const int tid = threadIdx.x;
    const int b = blockIdx.y;
    const int p = tid & 63;
    const int h = tid >> 6;              // 0..3
    const int n = blockIdx.x * 64 + p;
    for (int i = tid; i < OUT_ * C_; i += 256) WresS[i] = g_Wres[i];
    for (int i = tid; i < HB_ * C_; i += 256)  WbotS[i] = g_Wbot[i];
    if (tid < OUT_) bresS[tid] = g_bres[tid];
    if (tid < HB_)  bbotS[tid] = g_bbot[tid];
    __syncthreads();

    float xv[64];
#pragma unroll
    for (int c = 0; c < 64; c++) xv[c] = x[(b * C_ + c) * N_ + n];

    const int oR = h * 32;
#pragma unroll 4
    for (int oo = 0; oo < 32; oo++) {
        const int o = oR + oo;
        const float4* w4 = (const float4*)(WresS + o * 64);
        float s0 = 0.f, s1 = 0.f, s2 = 0.f, s3 = 0.f;
#pragma unroll
        for (int i = 0; i < 16; i++) {
            float4 wv = w4[i];
            s0 += wv.x * xv[4 * i + 0];
            s1 += wv.y * xv[4 * i + 1];
            s2 += wv.z * xv[4 * i + 2];
            s3 += wv.w * xv[4 * i + 3];
        }
        float acc = bresS[o] + ((s0 + s1) + (s2 + s3));
        out[(b * OUT_ + o) * N_ + n] = fmaxf(acc, 0.f);
    }
    const int oB = h * 4;
#pragma unroll
    for (int oo = 0; oo < 4; oo++) {
        const int o = oB + oo;
        const float4* w4 = (const float4*)(WbotS + o * 64);
        float s0 = 0.f, s1 = 0.f, s2 = 0.f, s3 = 0.f;
#pragma unroll
        for (int i = 0; i < 16; i++) {
            float4 wv = w4[i];
            s0 += wv.x * xv[4 * i + 0];
            s1 += wv.y * xv[4 * i + 1];
            s2 += wv.z * xv[4 * i + 2];
            s3 += wv.w * xv[4 * i + 3];
        }
        float acc = bbotS[o] + ((s0 + s1) + (s2 + s3));
        g_hb[(b * N_ + n) * HB_ + o] = fmaxf(acc, 0.f);
    }
}

// ---------------- kernel 3: d2 via bf16 mma, two-pass full hi/lo product ---
constexpr int SST = 136;   // smem row stride in bf16 (272B: conflict-free ldmatrix)

__global__ __launch_bounds__(256) void d2gemm_kernel() {
    extern __shared__ __nv_bfloat16 sm[];
    __nv_bfloat16* As = sm;
    __nv_bfloat16* Bs = sm + 128 * SST;
    const int tid = threadIdx.x;
    const int lane = tid & 31, warp = tid >> 5;
    const int b = blockIdx.z;
    const int m0 = blockIdx.y * 128, n0 = blockIdx.x * 128;
    const int mBase = (warp >> 2) * 64;
    const int nBase = (warp & 3) * 32;

    {
        const uint4* srcA = (const uint4*)(g_pbf + ((size_t)(b * N_ + m0)) * 128);
        const uint4* srcB = (const uint4*)(g_pbf + ((size_t)(b * N_ + n0)) * 128);
#pragma unroll
        for (int i = tid; i < 2048; i += 256) {
            int r = i >> 4, c = i & 15;
            *(uint4*)((char*)As + r * 272 + c * 16) = srcA[i];
            *(uint4*)((char*)Bs + r * 272 + c * 16) = srcB[i];
        }
    }
    __syncthreads();

    float acc[16][4];
#pragma unroll
    for (int t = 0; t < 16; t++) { acc[t][0] = acc[t][1] = acc[t][2] = acc[t][3] = 0.f; }

    unsigned aBase = (unsigned)__cvta_generic_to_shared(As)
                   + ((mBase + (lane & 15)) * SST + ((lane >> 4) << 3)) * 2;
    unsigned bBase = (unsigned)__cvta_generic_to_shared(Bs)
                   + ((nBase + (lane & 7) + ((lane >> 4) << 3)) * SST + (((lane >> 3) & 1) << 3)) * 2;

#pragma unroll
    for (int ks = 0; ks < 8; ks++) {
        unsigned a[4][4], bf[2][4], bx[2][4];
#pragma unroll
        for (int i = 0; i < 4; i++)
            ldsm4(a[i][0], a[i][1], a[i][2], a[i][3], aBase + i * (16 * SST * 2) + ks * 32);
#pragma unroll
        for (int i = 0; i < 2; i++)
            ldsm4(bf[i][0], bf[i][1], bf[i][2], bf[i][3], bBase + i * (16 * SST * 2) + ks * 32);
#pragma unroll
        for (int i = 0; i < 2; i++)
            ldsm4(bx[i][0], bx[i][1], bx[i][2], bx[i][3],
                  bBase + i * (16 * SST * 2) + (ks ^ 4) * 32);
#pragma unroll
        for (int i = 0; i < 4; i++)
#pragma unroll
            for (int j = 0; j < 4; j++) {
                mma16816(acc[i * 4 + j], a[i],
                         bf[j >> 1][(j & 1) << 1], bf[j >> 1][((j & 1) << 1) | 1]);
                mma16816(acc[i * 4 + j], a[i],
                         bx[j >> 1][(j & 1) << 1], bx[j >> 1][((j & 1) << 1) | 1]);
            }
    }

    // epilogue: d2 = sq[m] + sq[n] - 2*dot
    const float* sqB = g_sq + b * N_;
    float sm0[4], sm1[4], sn0[4], sn1[4];
#pragma unroll
    for (int i = 0; i < 4; i++) {
        int r = m0 + mBase + i * 16 + (lane >> 2);
        sm0[i] = sqB[r]; sm1[i] = sqB[r + 8];
    }
#pragma unroll
    for (int j = 0; j < 4; j++) {
        int c = n0 + nBase + j * 8 + ((lane & 3) << 1);
        sn0[j] = sqB[c]; sn1[j] = sqB[c + 1];
    }
    float* drow = g_d2 + (size_t)b * N_ * N_;
#pragma unroll
    for (int i = 0; i < 4; i++) {
        int r0 = m0 + mBase + i * 16 + (lane >> 2);
#pragma unroll
        for (int j = 0; j < 4; j++) {
            int c = n0 + nBase + j * 8 + ((lane & 3) << 1);
            const float* t0 = acc[i * 4 + j];
            float2 v0 = make_float2(fmaf(-2.f, t0[0], sm0[i] + sn0[j]),
                                    fmaf(-2.f, t0[1], sm0[i] + sn1[j]));
            float2 v1 = make_float2(fmaf(-2.f, t0[2], sm1[i] + sn0[j]),
                                    fmaf(-2.f, t0[3], sm1[i] + sn1[j]));
            *(float2*)(drow + (size_t)r0 * N_ + c)       = v0;
            *(float2*)(drow + (size_t)(r0 + 8) * N_ + c) = v1;
        }
    }
}

// ---------------- kernel 3b: warp-collective top-20 selection --------------
// ONE sorted-by-(d,idx) list per warp, one slot per lane (slots 0..31 ascending,
// only 0..19 are the answer). Ballot finds candidates vs thr=slot[19]; each
// insertion is a warp-parallel shfl-up shift. ~126 true insertions per row.
__global__ __launch_bounds__(256) void knn_select_kernel() {
    const int lane = threadIdx.x & 31, w = threadIdx.x >> 5;
    const int row = blockIdx.x * 8 + w;              // [0, B*N)
    const float4* dr = (const float4*)(g_d2 + (size_t)row * N_);

    float sd = 3.4e38f;        // this lane's list slot (distance)
    int   si = 0x7fffffff;     // this lane's list slot (index)
    float thrF = 3.4e38f;      // slot[19] distance, replicated

    for (int it = 0; it < N_ / 128; it++) {
        float4 v = dr[it * 32 + lane];
        float m4 = fminf(fminf(v.x, v.y), fminf(v.z, v.w));
        if (!__ballot_sync(0xffffffffu, m4 <= thrF)) continue;
        const int base = it * 128 + lane * 4;
#pragma unroll
        for (int c = 0; c < 4; c++) {
            float d = (c == 0) ? v.x : (c == 1) ? v.y : (c == 2) ? v.z : v.w;
            int idx = base + c;
            unsigned ball = __ballot_sync(0xffffffffu, d <= thrF);
            while (ball) {
                int src = __ffs(ball) - 1;
                float nd = __shfl_sync(0xffffffffu, d, src);
                int   ni = __shfl_sync(0xffffffffu, idx, src);
                // warp-collective sorted insert of (nd, ni)
                bool pred = (sd > nd) || (sd == nd && si > ni);
                unsigned pb = __ballot_sync(0xffffffffu, pred);
                if (pb) {
                    int p = __ffs(pb) - 1;
                    float shd = __shfl_up_sync(0xffffffffu, sd, 1);
                    int   shi = __shfl_up_sync(0xffffffffu, si, 1);
                    if (lane > p)  { sd = shd; si = shi; }
                    if (lane == p) { sd = nd;  si = ni;  }
                    thrF = __shfl_sync(0xffffffffu, sd, 19);
                }
                ball &= ~(1u << src);
                ball &= __ballot_sync(0xffffffffu, d <= thrF);   // re-check vs tightened thr
            }
        }
    }
    if (lane < K_) g_idx[row * K_ + lane] = si;      // slots 0..19 = exact sorted top-20
}

// ---------------- kernel 4: fused GCN (gather, g1, g2, gmax, decode) -------
__device__ __forceinline__ float dot16(const float* wv,
                                       float4 v0, float4 v1, float4 v2, float4 v3) {
    return wv[0] * v0.x + wv[1] * v0.y + wv[2]  * v0.z + wv[3]  * v0.w
         + wv[4] * v1.x + wv[5] * v1.y + wv[6]  * v1.z + wv[7]  * v1.w
         + wv[8] * v2.x + wv[9] * v2.y + wv[10] * v2.z + wv[11] * v2.w
         + wv[12]* v3.x + wv[13]* v3.y + wv[14] * v3.z + wv[15] * v3.w;
}

constexpr int WPB = 8;       // warps (points) per block
constexpr int WD_PAD = 100;  // padded row stride for Wdec (conflict-free float4)

__global__ __launch_bounds__(256) void gcn_kernel(float* __restrict__ out) {
    extern __shared__ float WdP[];              // [128][100] padded decode weights
    __shared__ float nbS[WPB][K_][HB_];
    __shared__ float ctrS[WPB][HB_];
    __shared__ float allfS[WPB][96];
    __shared__ int   idxS[WPB][K_];

    const int tid = threadIdx.x;
    const int w = tid >> 5, lane = tid & 31;
    const int b = blockIdx.y;
    const int n = blockIdx.x * WPB + w;

    for (int i = tid; i < OUT_ * 96; i += 256) {
        int o = i / 96, c = i - o * 96;
        WdP[o * WD_PAD + c] = g_Wdec[i];
    }

    float w1[32], w2[32];
    {
        const float4* w1p = (const float4*)(g_Wg1 + lane * 32);
        const float4* w2p = (const float4*)(g_Wg2 + lane * 32);
#pragma unroll
        for (int c4 = 0; c4 < 8; c4++) {
            float4 t1 = w1p[c4];
            w1[c4 * 4 + 0] = t1.x; w1[c4 * 4 + 1] = t1.y;
            w1[c4 * 4 + 2] = t1.z; w1[c4 * 4 + 3] = t1.w;
            float4 t2 = w2p[c4];
            w2[c4 * 4 + 0] = t2.x; w2[c4 * 4 + 1] = t2.y;
            w2[c4 * 4 + 2] = t2.z; w2[c4 * 4 + 3] = t2.w;
        }
    }
    const float b1 = g_bg1[lane], b2 = g_bg2[lane];

    if (lane < K_)  idxS[w][lane] = g_idx[(b * N_ + n) * K_ + lane];
    if (lane < HB_) ctrS[w][lane] = g_hb[(b * N_ + n) * HB_ + lane];
    __syncwarp();

    for (int t = lane; t < K_ * HB_; t += 32) {
        int k = t >> 4, c = t & 15;
        nbS[w][k][c] = g_hb[(b * N_ + idxS[w][k]) * HB_ + c];
    }
    __syncthreads();   // also covers WdP load

    float pre1 = b1, pre2 = b2;
#pragma unroll
    for (int c = 0; c < 16; c++) {
        float cv = ctrS[w][c];
        pre1 += w1[16 + c] * cv;
        pre2 += w2[16 + c] * cv;
    }

    float acc1 = -3.4e38f, acc2 = -3.4e38f;
#pragma unroll
    for (int k = 0; k < K_; k++) {
        const float4* nb4 = (const float4*)nbS[w][k];
        float4 v0 = nb4[0], v1 = nb4[1], v2 = nb4[2], v3 = nb4[3];
        float y = pre1 + dot16(w1, v0, v1, v2, v3);
        float ly = y > 0.f ? y : 0.2f * y;
        acc1 = fmaxf(acc1, ly);
        if ((k & 1) == 0) {
            float y2 = pre2 + dot16(w2, v0, v1, v2, v3);
            float ly2 = y2 > 0.f ? y2 : 0.2f * y2;
            acc2 = fmaxf(acc2, ly2);
        }
    }

    float gm = -3.4e38f;
    if (lane < 16) {
#pragma unroll
        for (int k = 0; k < K_; k++) gm = fmaxf(gm, nbS[w][k][lane]);
    }
    allfS[w][lane]      = acc1;
    allfS[w][32 + lane] = acc2;
    allfS[w][64 + lane] = (lane < 16) ? gm : ctrS[w][lane - 16];
    __syncwarp();

    float accd0 = g_bdec[lane],      accd1 = g_bdec[lane + 32];
    float accd2 = g_bdec[lane + 64], accd3 = g_bdec[lane + 96];
    const float4* af4 = (const float4*)allfS[w];
    const float4* wr0 = (const float4*)(WdP + (lane)      * WD_PAD);
    const float4* wr1 = (const float4*)(WdP + (lane + 32) * WD_PAD);
    const float4* wr2 = (const float4*)(WdP + (lane + 64) * WD_PAD);
    const float4* wr3 = (const float4*)(WdP + (lane + 96) * WD_PAD);
#pragma unroll
    for (int c4 = 0; c4 < 24; c4++) {
        float4 a = af4[c4];
        float4 q0 = wr0[c4]; accd0 += q0.x*a.x + q0.y*a.y + q0.z*a.z + q0.w*a.w;
        float4 q1 = wr1[c4]; accd1 += q1.x*a.x + q1.y*a.y + q1.z*a.z + q1.w*a.w;
        float4 q2 = wr2[c4]; accd2 += q2.x*a.x + q2.y*a.y + q2.z*a.z + q2.w*a.w;
        float4 q3 = wr3[c4]; accd3 += q3.x*a.x + q3.y*a.y + q3.z*a.z + q3.w*a.w;
    }
    {
        int i0 = (b * OUT_ + lane)      * N_ + n;
        int i1 = (b * OUT_ + lane + 32) * N_ + n;
        int i2 = (b * OUT_ + lane + 64) * N_ + n;
        int i3 = (b * OUT_ + lane + 96) * N_ + n;
        float r0 = out[i0], r1 = out[i1], r2 = out[i2], r3 = out[i3];
        out[i0] = fmaxf(accd0, 0.f) + r0;
        out[i1] = fmaxf(accd1, 0.f) + r1;
        out[i2] = fmaxf(accd2, 0.f) + r2;
        out[i3] = fmaxf(accd3, 0.f) + r3;
    }
}

// ---------------- launch ---------------------------------------------------
extern "C" void kernel_launch(void* const* d_in, const int* in_sizes, int n_in,
                              void* d_out, int out_size) {
    Params P;
    for (int i = 0; i < 26; i++) P.p[i] = (const float*)d_in[i];
    const float* x = P.p[0];
    float* out = (float*)d_out;

    const int gemm_smem = 2 * 128 * SST * (int)sizeof(__nv_bfloat16);   // 69632 B
    cudaFuncSetAttribute(d2gemm_kernel, cudaFuncAttributeMaxDynamicSharedMemorySize, gemm_smem);
    cudaFuncSetAttribute(gcn_kernel, cudaFuncAttributeMaxDynamicSharedMemorySize,
                         OUT_ * WD_PAD * (int)sizeof(float));

    fold_kernel<<<1, 256>>>(P);
    prep_kernel<<<dim3(N_ / 64, B_), 256>>>(x);
    conv1_kernel<<<dim3(N_ / 64, B_), 256>>>(x, out);
    d2gemm_kernel<<<dim3(N_ / 128, N_ / 128, B_), 256, gemm_smem>>>();
    knn_select_kernel<<<(B_ * N_) / 8, 256>>>();
    gcn_kernel<<<dim3(N_ / WPB, B_), 256, OUT_ * WD_PAD * (int)sizeof(float)>>>(out);
}